// round 6
// baseline (speedup 1.0000x reference)
#include <cuda_runtime.h>
#include <math.h>
#include <stdint.h>

// Flash attention, tensor-core tf32, 512 threads (16 warps) per CTA for latency hiding.
// QK^T: full 3-term hi/lo split -> score err ~1e-7
// P@V : plain tf32 -> ~3e-4 rel err (gate 1e-3)
// S=8192, D=128. CTA: BM=64 rows, 128 tiles of BN=64.
// QK: warp grid 4 row x 4 col (m16n16). PV: 4 row x 4 dcol (m16n32).

namespace {
constexpr int S_TOTAL  = 8192;
constexpr int D_DIM    = 128;
constexpr int BM       = 64;
constexpr int BN       = 64;
constexpr int NTHREADS = 512;
constexpr int QK_STRIDE = 132;   // Qh/Ql/Kh/Kl row stride
constexpr int VS_STRIDE = 136;   // Vh row stride (conflict-free scalar frag reads)
constexpr int P_STRIDE  = 68;    // Ps row stride
constexpr int NTILES    = S_TOTAL / BN;

constexpr int OFF_QH    = 0;
constexpr int OFF_QL    = OFF_QH + BM * QK_STRIDE;
constexpr int OFF_KH    = OFF_QL + BM * QK_STRIDE;
constexpr int OFF_KL    = OFF_KH + BN * QK_STRIDE;
constexpr int OFF_VH    = OFF_KL + BN * QK_STRIDE;
constexpr int OFF_P     = OFF_VH + BN * VS_STRIDE;
constexpr int OFF_RM    = OFF_P + BM * P_STRIDE;     // red max [64][4]
constexpr int OFF_RS    = OFF_RM + BM * 4;           // red sum [64][4]
constexpr int OFF_ROWM  = OFF_RS + BM * 4;
constexpr int OFF_ROWL  = OFF_ROWM + BM;
constexpr int OFF_ROWSC = OFF_ROWL + BM;
constexpr int SMEM_FLOATS = OFF_ROWSC + BM;          // ~47.5K floats ~= 190 KB
}  // namespace

__device__ __forceinline__ int perm8(int c) {
    return ((c & 3) << 1) | ((c >> 2) & 1);
}

__device__ __forceinline__ void split_tf32(float x, uint32_t& hi, uint32_t& lo) {
    uint32_t h;
    asm("cvt.rna.tf32.f32 %0, %1;" : "=r"(h) : "f"(x));
    float r = x - __uint_as_float(h);
    asm("cvt.rna.tf32.f32 %0, %1;" : "=r"(lo) : "f"(r));
    hi = h;
}

__device__ __forceinline__ uint32_t tf32_rna(float x) {
    uint32_t h;
    asm("cvt.rna.tf32.f32 %0, %1;" : "=r"(h) : "f"(x));
    return h;
}

__device__ __forceinline__ void mma8(float* c,
                                     uint32_t a0, uint32_t a1, uint32_t a2, uint32_t a3,
                                     uint32_t b0, uint32_t b1) {
    asm volatile(
        "mma.sync.aligned.m16n8k8.row.col.f32.tf32.tf32.f32 "
        "{%0,%1,%2,%3}, {%4,%5,%6,%7}, {%8,%9}, {%0,%1,%2,%3};\n"
        : "+f"(c[0]), "+f"(c[1]), "+f"(c[2]), "+f"(c[3])
        : "r"(a0), "r"(a1), "r"(a2), "r"(a3), "r"(b0), "r"(b1));
}

__device__ __forceinline__ void mma8_split(float* c,
                                           const uint32_t ah[4], const uint32_t al[4],
                                           uint32_t bh0, uint32_t bh1,
                                           uint32_t bl0, uint32_t bl1) {
    mma8(c, ah[0], ah[1], ah[2], ah[3], bh0, bh1);
    mma8(c, ah[0], ah[1], ah[2], ah[3], bl0, bl1);
    mma8(c, al[0], al[1], al[2], al[3], bh0, bh1);
}

__device__ __forceinline__ void store_perm4_split(float* hrow, float* lrow, int c4, float4 v) {
    int blk = (c4 * 4) & ~7;
    int lo4 = (c4 & 1) * 4;
    uint32_t h, l;
    split_tf32(v.x, h, l);
    hrow[blk + perm8(lo4 + 0)] = __uint_as_float(h);
    lrow[blk + perm8(lo4 + 0)] = __uint_as_float(l);
    split_tf32(v.y, h, l);
    hrow[blk + perm8(lo4 + 1)] = __uint_as_float(h);
    lrow[blk + perm8(lo4 + 1)] = __uint_as_float(l);
    split_tf32(v.z, h, l);
    hrow[blk + perm8(lo4 + 2)] = __uint_as_float(h);
    lrow[blk + perm8(lo4 + 2)] = __uint_as_float(l);
    split_tf32(v.w, h, l);
    hrow[blk + perm8(lo4 + 3)] = __uint_as_float(h);
    lrow[blk + perm8(lo4 + 3)] = __uint_as_float(l);
}

__global__ __launch_bounds__(NTHREADS, 1)
void fa_tf32_kernel(const float* __restrict__ gq,
                    const float* __restrict__ gk,
                    const float* __restrict__ gv,
                    float* __restrict__ gout) {
    extern __shared__ float sm[];
    float* Qh     = sm + OFF_QH;
    float* Ql     = sm + OFF_QL;
    float* Kh     = sm + OFF_KH;
    float* Kl     = sm + OFF_KL;
    float* Vh     = sm + OFF_VH;
    float* Ps     = sm + OFF_P;
    float* red_m  = sm + OFF_RM;
    float* red_s  = sm + OFF_RS;
    float* row_m  = sm + OFF_ROWM;
    float* row_l  = sm + OFF_ROWL;
    float* row_sc = sm + OFF_ROWSC;

    const int tid  = threadIdx.x;
    const int lane = tid & 31;
    const int warp = tid >> 5;
    const int wr   = warp & 3;       // row group: rows [wr*16, wr*16+16)
    const int wc   = warp >> 2;      // col group 0..3
    const int lq   = lane & 3;
    const int lr   = lane >> 2;
    const int r0   = wr * 16 + lr;   // rows r0 and r0+8 owned by this thread

    const int qbase = blockIdx.x * BM;
    const float4* gq4 = reinterpret_cast<const float4*>(gq);
    const float4* gk4 = reinterpret_cast<const float4*>(gk);
    const float4* gv4 = reinterpret_cast<const float4*>(gv);

    // ---- load + split Q tile once ----
#pragma unroll
    for (int it = 0; it < (BM * D_DIM / 4) / NTHREADS; ++it) {
        int idx = it * NTHREADS + tid;
        int row = idx >> 5;
        int c4  = idx & 31;
        float4 v = gq4[(size_t)(qbase + row) * (D_DIM / 4) + c4];
        store_perm4_split(&Qh[row * QK_STRIDE], &Ql[row * QK_STRIDE], c4, v);
    }
    if (tid < BM) { row_m[tid] = -INFINITY; row_l[tid] = 0.0f; }

    float acc_o[4][4];
#pragma unroll
    for (int n = 0; n < 4; ++n)
#pragma unroll
        for (int j = 0; j < 4; ++j) acc_o[n][j] = 0.0f;

    const float sm_scale = 0.08838834764831845f;  // 1/sqrt(128)

    for (int t = 0; t < NTILES; ++t) {
        __syncthreads();  // protect tiles from previous iteration readers
        const int kb = t * BN;

        // ---- load + split K; load V (tf32-rounded) ----
#pragma unroll
        for (int it = 0; it < (BN * D_DIM / 4) / NTHREADS; ++it) {
            int idx = it * NTHREADS + tid;
            int row = idx >> 5;
            int c4  = idx & 31;
            float4 v = gk4[(size_t)(kb + row) * (D_DIM / 4) + c4];
            store_perm4_split(&Kh[row * QK_STRIDE], &Kl[row * QK_STRIDE], c4, v);
        }
#pragma unroll
        for (int it = 0; it < (BN * D_DIM / 4) / NTHREADS; ++it) {
            int idx = it * NTHREADS + tid;
            int s   = idx >> 5;
            int c4  = idx & 31;
            float4 v = gv4[(size_t)(kb + s) * (D_DIM / 4) + c4];
            float4 hv;
            hv.x = __uint_as_float(tf32_rna(v.x));
            hv.y = __uint_as_float(tf32_rna(v.y));
            hv.z = __uint_as_float(tf32_rna(v.z));
            hv.w = __uint_as_float(tf32_rna(v.w));
            *reinterpret_cast<float4*>(&Vh[s * VS_STRIDE + c4 * 4]) = hv;
        }
        __syncthreads();

        // ---- S = Q K^T : warp m16 x n16, 3-term split ----
        float sc[2][4];
#pragma unroll
        for (int n = 0; n < 2; ++n)
#pragma unroll
            for (int j = 0; j < 4; ++j) sc[n][j] = 0.0f;

#pragma unroll
        for (int ks = 0; ks < D_DIM / 8; ++ks) {
            const int k0 = ks * 8;
            float2 qah = *reinterpret_cast<const float2*>(&Qh[r0 * QK_STRIDE + k0 + 2 * lq]);
            float2 qbh = *reinterpret_cast<const float2*>(&Qh[(r0 + 8) * QK_STRIDE + k0 + 2 * lq]);
            float2 qal = *reinterpret_cast<const float2*>(&Ql[r0 * QK_STRIDE + k0 + 2 * lq]);
            float2 qbl = *reinterpret_cast<const float2*>(&Ql[(r0 + 8) * QK_STRIDE + k0 + 2 * lq]);
            uint32_t ah[4] = { __float_as_uint(qah.x), __float_as_uint(qbh.x),
                               __float_as_uint(qah.y), __float_as_uint(qbh.y) };
            uint32_t al[4] = { __float_as_uint(qal.x), __float_as_uint(qbl.x),
                               __float_as_uint(qal.y), __float_as_uint(qbl.y) };
#pragma unroll
            for (int nt = 0; nt < 2; ++nt) {
                const int n0 = wc * 16 + nt * 8;
                float2 kvh = *reinterpret_cast<const float2*>(&Kh[(n0 + lr) * QK_STRIDE + k0 + 2 * lq]);
                float2 kvl = *reinterpret_cast<const float2*>(&Kl[(n0 + lr) * QK_STRIDE + k0 + 2 * lq]);
                mma8_split(sc[nt], ah, al,
                           __float_as_uint(kvh.x), __float_as_uint(kvh.y),
                           __float_as_uint(kvl.x), __float_as_uint(kvl.y));
            }
        }

        // ---- softmax stats ----
        float mr = -INFINITY, mr8 = -INFINITY;
#pragma unroll
        for (int nt = 0; nt < 2; ++nt) {
            sc[nt][0] *= sm_scale; sc[nt][1] *= sm_scale;
            sc[nt][2] *= sm_scale; sc[nt][3] *= sm_scale;
            mr  = fmaxf(mr,  fmaxf(sc[nt][0], sc[nt][1]));
            mr8 = fmaxf(mr8, fmaxf(sc[nt][2], sc[nt][3]));
        }
        mr  = fmaxf(mr,  __shfl_xor_sync(0xffffffffu, mr, 1));
        mr  = fmaxf(mr,  __shfl_xor_sync(0xffffffffu, mr, 2));
        mr8 = fmaxf(mr8, __shfl_xor_sync(0xffffffffu, mr8, 1));
        mr8 = fmaxf(mr8, __shfl_xor_sync(0xffffffffu, mr8, 2));
        if (lq == 0) {
            red_m[r0 * 4 + wc]       = mr;
            red_m[(r0 + 8) * 4 + wc] = mr8;
        }
        __syncthreads();

        if (tid < BM) {
            float mo = row_m[tid];
            float mn = fmaxf(fmaxf(red_m[tid * 4], red_m[tid * 4 + 1]),
                             fmaxf(red_m[tid * 4 + 2], red_m[tid * 4 + 3]));
            mn = fmaxf(mo, mn);
            row_m[tid]  = mn;
            row_sc[tid] = __expf(mo - mn);  // 0 on first tile
        }
        __syncthreads();

        // ---- exp, write P (perm cols), partial row sums ----
        const float mrow  = row_m[r0];
        const float mrow8 = row_m[r0 + 8];
        float s_r = 0.0f, s_r8 = 0.0f;
        const int o0 = perm8(2 * lq);
        const int o1 = perm8(2 * lq + 1);
#pragma unroll
        for (int nt = 0; nt < 2; ++nt) {
            const int cb = wc * 16 + nt * 8;
            float p00 = __expf(sc[nt][0] - mrow);
            float p01 = __expf(sc[nt][1] - mrow);
            float p10 = __expf(sc[nt][2] - mrow8);
            float p11 = __expf(sc[nt][3] - mrow8);
            s_r  += p00 + p01;
            s_r8 += p10 + p11;
            Ps[r0 * P_STRIDE + cb + o0]       = p00;
            Ps[r0 * P_STRIDE + cb + o1]       = p01;
            Ps[(r0 + 8) * P_STRIDE + cb + o0] = p10;
            Ps[(r0 + 8) * P_STRIDE + cb + o1] = p11;
        }
        s_r  += __shfl_xor_sync(0xffffffffu, s_r, 1);
        s_r  += __shfl_xor_sync(0xffffffffu, s_r, 2);
        s_r8 += __shfl_xor_sync(0xffffffffu, s_r8, 1);
        s_r8 += __shfl_xor_sync(0xffffffffu, s_r8, 2);
        if (lq == 0) {
            red_s[r0 * 4 + wc]       = s_r;
            red_s[(r0 + 8) * 4 + wc] = s_r8;
        }

        // rescale O accumulators
        const float f0 = row_sc[r0];
        const float f1 = row_sc[r0 + 8];
#pragma unroll
        for (int nt = 0; nt < 4; ++nt) {
            acc_o[nt][0] *= f0; acc_o[nt][1] *= f0;
            acc_o[nt][2] *= f1; acc_o[nt][3] *= f1;
        }
        __syncthreads();

        if (tid < BM)
            row_l[tid] = row_l[tid] * row_sc[tid] +
                         (red_s[tid * 4] + red_s[tid * 4 + 1]) +
                         (red_s[tid * 4 + 2] + red_s[tid * 4 + 3]);

        // ---- O += P V : warp m16 x n32 (d-quarter), plain tf32 ----
#pragma unroll
        for (int ks = 0; ks < BN / 8; ++ks) {
            const int k0 = ks * 8;
            float2 pa = *reinterpret_cast<const float2*>(&Ps[r0 * P_STRIDE + k0 + 2 * lq]);
            float2 pb = *reinterpret_cast<const float2*>(&Ps[(r0 + 8) * P_STRIDE + k0 + 2 * lq]);
            uint32_t ah0 = tf32_rna(pa.x);
            uint32_t ah1 = tf32_rna(pb.x);
            uint32_t ah2 = tf32_rna(pa.y);
            uint32_t ah3 = tf32_rna(pb.y);
#pragma unroll
            for (int nt = 0; nt < 4; ++nt) {
                const int n0 = wc * 32 + nt * 8;
                // bank = (8*lq + lr) across warp: conflict-free scalar reads
                float v0h = Vh[(k0 + lq) * VS_STRIDE + n0 + lr];
                float v1h = Vh[(k0 + lq + 4) * VS_STRIDE + n0 + lr];
                mma8(acc_o[nt], ah0, ah1, ah2, ah3,
                     __float_as_uint(v0h), __float_as_uint(v1h));
            }
        }
    }

    __syncthreads();

    // ---- normalize + store ----
    const float inv0 = 1.0f / row_l[r0];
    const float inv1 = 1.0f / row_l[r0 + 8];
#pragma unroll
    for (int nt = 0; nt < 4; ++nt) {
        const int d0 = wc * 32 + nt * 8 + 2 * lq;
        float2 oa, ob;
        oa.x = acc_o[nt][0] * inv0; oa.y = acc_o[nt][1] * inv0;
        ob.x = acc_o[nt][2] * inv1; ob.y = acc_o[nt][3] * inv1;
        *reinterpret_cast<float2*>(&gout[(size_t)(qbase + r0) * D_DIM + d0])     = oa;
        *reinterpret_cast<float2*>(&gout[(size_t)(qbase + r0 + 8) * D_DIM + d0]) = ob;
    }
}

extern "C" void kernel_launch(void* const* d_in, const int* in_sizes, int n_in,
                              void* d_out, int out_size) {
    const float* q = (const float*)d_in[0];
    const float* k = (const float*)d_in[1];
    const float* v = (const float*)d_in[2];
    float* out = (float*)d_out;
    (void)in_sizes; (void)n_in; (void)out_size;

    const int smem_bytes = SMEM_FLOATS * (int)sizeof(float);
    cudaFuncSetAttribute(fa_tf32_kernel,
                         cudaFuncAttributeMaxDynamicSharedMemorySize, smem_bytes);
    fa_tf32_kernel<<<S_TOTAL / BM, NTHREADS, smem_bytes>>>(q, k, v, out);
}

// round 7
// speedup vs baseline: 2.6067x; 2.6067x over previous
#include <cuda_runtime.h>
#include <cuda_fp16.h>
#include <math.h>
#include <stdint.h>

// Flash attention, fp16 tensor cores (m16n8k16), fp32 accumulate.
// QK^T: 3-term hi/lo fp16 split (~22 mantissa bits)  -> score err negligible
// P@V : plain fp16 (11 bits, same as tf32)           -> ~2.8e-4 rel err, gate 1e-3
// S=8192, D=128. CTA: 256 threads (8 warps), BM=64 rows, 128 tiles of BN=64.
// QK: warp grid 4 row x 2 col (m16n32). PV: 4 row x 2 dcol (m16n64).
// fp16 tiles use perm16 k-interleave: cols {2t,2t+1,2t+8,2t+9} adjacent -> LDS.64 frags.

namespace {
constexpr int S_TOTAL  = 8192;
constexpr int D_DIM    = 128;
constexpr int BM       = 64;
constexpr int BN       = 64;
constexpr int NTHREADS = 256;
constexpr int NTILES   = S_TOTAL / BN;

constexpr int QK_ST = 72;    // Qh/Ql/Kh/Kl row stride in uint32 words (=144 fp16); 72%32=8 -> conflict-free
constexpr int P_ST  = 40;    // Ps row stride in words (=80 fp16); 40%32=8
constexpr int VS_ST = 132;   // Vs row stride in floats; 2*132%32=8 -> k-pair reads conflict-free

// smem layout in uint32 words
constexpr int OFF_QH = 0;
constexpr int OFF_QL = OFF_QH + BM * QK_ST;
constexpr int OFF_KH = OFF_QL + BM * QK_ST;
constexpr int OFF_KL = OFF_KH + BN * QK_ST;
constexpr int OFF_P  = OFF_KL + BN * QK_ST;
constexpr int OFF_V  = OFF_P  + BM * P_ST;           // float region
constexpr int OFF_RM = OFF_V  + BN * VS_ST;          // red max [64][2] (float)
constexpr int OFF_RS = OFF_RM + BM * 2;              // red sum [64][2]
constexpr int OFF_ROWM  = OFF_RS + BM * 2;
constexpr int OFF_ROWL  = OFF_ROWM + BM;
constexpr int OFF_ROWSC = OFF_ROWL + BM;
constexpr int SMEM_WORDS = OFF_ROWSC + BM;           // ~29.9K words ~= 120 KB
}  // namespace

__device__ __forceinline__ uint32_t packh2(float a, float b) {
    __half2 h = __floats2half2_rn(a, b);
    return *reinterpret_cast<uint32_t*>(&h);
}

// split (x,y) into fp16 hi pair and lo (residual) pair
__device__ __forceinline__ void split2_f16(float x, float y, uint32_t& hi, uint32_t& lo) {
    __half hx = __float2half_rn(x);
    __half hy = __float2half_rn(y);
    __half2 hh = __halves2half2(hx, hy);
    hi = *reinterpret_cast<uint32_t*>(&hh);
    lo = packh2(x - __half2float(hx), y - __half2float(hy));
}

__device__ __forceinline__ void mma16(float* c,
                                      uint32_t a0, uint32_t a1, uint32_t a2, uint32_t a3,
                                      uint32_t b0, uint32_t b1) {
    asm volatile(
        "mma.sync.aligned.m16n8k16.row.col.f32.f16.f16.f32 "
        "{%0,%1,%2,%3}, {%4,%5,%6,%7}, {%8,%9}, {%0,%1,%2,%3};\n"
        : "+f"(c[0]), "+f"(c[1]), "+f"(c[2]), "+f"(c[3])
        : "r"(a0), "r"(a1), "r"(a2), "r"(a3), "r"(b0), "r"(b1));
}

// store 4 consecutive k-cols (base 4*c4) of one row, split hi/lo, perm16 layout.
// word offsets within row: w0 = blk*8 + (b&1)*4 + (b>>1), pairs (j0,j1)@w0, (j2,j3)@w0+2
__device__ __forceinline__ void store4_split(uint32_t* rowh, uint32_t* rowl, int c4, float4 v) {
    int blk = c4 >> 2, b = c4 & 3;
    int w0 = blk * 8 + (b & 1) * 4 + (b >> 1);
    uint32_t h01, l01, h23, l23;
    split2_f16(v.x, v.y, h01, l01);
    split2_f16(v.z, v.w, h23, l23);
    rowh[w0]     = h01;
    rowl[w0]     = l01;
    rowh[w0 + 2] = h23;
    rowl[w0 + 2] = l23;
}

__global__ __launch_bounds__(NTHREADS, 1)
void fa_f16_kernel(const float* __restrict__ gq,
                   const float* __restrict__ gk,
                   const float* __restrict__ gv,
                   float* __restrict__ gout) {
    extern __shared__ uint32_t smw[];
    uint32_t* Qh = smw + OFF_QH;
    uint32_t* Ql = smw + OFF_QL;
    uint32_t* Kh = smw + OFF_KH;
    uint32_t* Kl = smw + OFF_KL;
    uint32_t* Ps = smw + OFF_P;
    float* Vs     = reinterpret_cast<float*>(smw + OFF_V);
    float* red_m  = reinterpret_cast<float*>(smw + OFF_RM);
    float* red_s  = reinterpret_cast<float*>(smw + OFF_RS);
    float* row_m  = reinterpret_cast<float*>(smw + OFF_ROWM);
    float* row_l  = reinterpret_cast<float*>(smw + OFF_ROWL);
    float* row_sc = reinterpret_cast<float*>(smw + OFF_ROWSC);

    const int tid  = threadIdx.x;
    const int lane = tid & 31;
    const int warp = tid >> 5;
    const int wr   = warp & 3;       // row group: rows [wr*16, wr*16+16)
    const int wc   = warp >> 2;      // col half
    const int lq   = lane & 3;       // t
    const int lr   = lane >> 2;      // g
    const int r0   = wr * 16 + lr;

    const int qbase = blockIdx.x * BM;
    const float4* gq4 = reinterpret_cast<const float4*>(gq);
    const float4* gk4 = reinterpret_cast<const float4*>(gk);
    const float4* gv4 = reinterpret_cast<const float4*>(gv);

    const float sm_scale = 0.08838834764831845f;  // 1/sqrt(128), folded into Q

    // ---- load + scale + split Q tile once ----
#pragma unroll
    for (int it = 0; it < (BM * D_DIM / 4) / NTHREADS; ++it) {
        int idx = it * NTHREADS + tid;
        int row = idx >> 5;
        int c4  = idx & 31;
        float4 v = gq4[(size_t)(qbase + row) * (D_DIM / 4) + c4];
        v.x *= sm_scale; v.y *= sm_scale; v.z *= sm_scale; v.w *= sm_scale;
        store4_split(&Qh[row * QK_ST], &Ql[row * QK_ST], c4, v);
    }
    if (tid < BM) { row_m[tid] = -INFINITY; row_l[tid] = 0.0f; }

    float acc_o[8][4];
#pragma unroll
    for (int n = 0; n < 8; ++n)
#pragma unroll
        for (int j = 0; j < 4; ++j) acc_o[n][j] = 0.0f;

    for (int t = 0; t < NTILES; ++t) {
        __syncthreads();  // protect tiles from previous iteration readers
        const int kb = t * BN;

        // ---- load + split K; load V (fp32, straight rows) ----
#pragma unroll
        for (int it = 0; it < (BN * D_DIM / 4) / NTHREADS; ++it) {
            int idx = it * NTHREADS + tid;
            int row = idx >> 5;
            int c4  = idx & 31;
            float4 v = gk4[(size_t)(kb + row) * (D_DIM / 4) + c4];
            store4_split(&Kh[row * QK_ST], &Kl[row * QK_ST], c4, v);
        }
#pragma unroll
        for (int it = 0; it < (BN * D_DIM / 4) / NTHREADS; ++it) {
            int idx = it * NTHREADS + tid;
            int s   = idx >> 5;
            int c4  = idx & 31;
            float4 v = gv4[(size_t)(kb + s) * (D_DIM / 4) + c4];
            *reinterpret_cast<float4*>(&Vs[s * VS_ST + c4 * 4]) = v;
        }
        __syncthreads();

        // ---- S = (Q*scale) K^T : 3-term fp16 split, warp m16 x n32 ----
        float sc[4][4];
#pragma unroll
        for (int n = 0; n < 4; ++n)
#pragma unroll
            for (int j = 0; j < 4; ++j) sc[n][j] = 0.0f;

#pragma unroll
        for (int ks = 0; ks < D_DIM / 16; ++ks) {
            const int kw = ks * 8 + 2 * lq;
            uint2 a02h = *reinterpret_cast<const uint2*>(&Qh[r0 * QK_ST + kw]);
            uint2 a13h = *reinterpret_cast<const uint2*>(&Qh[(r0 + 8) * QK_ST + kw]);
            uint2 a02l = *reinterpret_cast<const uint2*>(&Ql[r0 * QK_ST + kw]);
            uint2 a13l = *reinterpret_cast<const uint2*>(&Ql[(r0 + 8) * QK_ST + kw]);
#pragma unroll
            for (int nt = 0; nt < 4; ++nt) {
                const int n0 = wc * 32 + nt * 8;
                uint2 bh = *reinterpret_cast<const uint2*>(&Kh[(n0 + lr) * QK_ST + kw]);
                uint2 bl = *reinterpret_cast<const uint2*>(&Kl[(n0 + lr) * QK_ST + kw]);
                mma16(sc[nt], a02h.x, a13h.x, a02h.y, a13h.y, bh.x, bh.y);
                mma16(sc[nt], a02h.x, a13h.x, a02h.y, a13h.y, bl.x, bl.y);
                mma16(sc[nt], a02l.x, a13l.x, a02l.y, a13l.y, bh.x, bh.y);
            }
        }

        // ---- softmax stats (scores already scaled) ----
        float mr = -INFINITY, mr8 = -INFINITY;
#pragma unroll
        for (int nt = 0; nt < 4; ++nt) {
            mr  = fmaxf(mr,  fmaxf(sc[nt][0], sc[nt][1]));
            mr8 = fmaxf(mr8, fmaxf(sc[nt][2], sc[nt][3]));
        }
        mr  = fmaxf(mr,  __shfl_xor_sync(0xffffffffu, mr, 1));
        mr  = fmaxf(mr,  __shfl_xor_sync(0xffffffffu, mr, 2));
        mr8 = fmaxf(mr8, __shfl_xor_sync(0xffffffffu, mr8, 1));
        mr8 = fmaxf(mr8, __shfl_xor_sync(0xffffffffu, mr8, 2));
        if (lq == 0) {
            red_m[r0 * 2 + wc]       = mr;
            red_m[(r0 + 8) * 2 + wc] = mr8;
        }
        __syncthreads();

        if (tid < BM) {
            float mo = row_m[tid];
            float mn = fmaxf(mo, fmaxf(red_m[tid * 2], red_m[tid * 2 + 1]));
            row_m[tid]  = mn;
            row_sc[tid] = __expf(mo - mn);  // 0 on first tile
        }
        __syncthreads();

        // ---- exp, write P (fp16, perm16 cols), partial row sums ----
        const float mrow  = row_m[r0];
        const float mrow8 = row_m[r0 + 8];
        float s_r = 0.0f, s_r8 = 0.0f;
#pragma unroll
        for (int nt = 0; nt < 4; ++nt) {
            const int cb  = wc * 32 + nt * 8;
            const int blk = cb >> 4;          // 16-col block
            const int w   = blk * 8 + 2 * lq + (nt & 1);
            float p00 = __expf(sc[nt][0] - mrow);
            float p01 = __expf(sc[nt][1] - mrow);
            float p10 = __expf(sc[nt][2] - mrow8);
            float p11 = __expf(sc[nt][3] - mrow8);
            s_r  += p00 + p01;
            s_r8 += p10 + p11;
            Ps[r0 * P_ST + w]       = packh2(p00, p01);
            Ps[(r0 + 8) * P_ST + w] = packh2(p10, p11);
        }
        s_r  += __shfl_xor_sync(0xffffffffu, s_r, 1);
        s_r  += __shfl_xor_sync(0xffffffffu, s_r, 2);
        s_r8 += __shfl_xor_sync(0xffffffffu, s_r8, 1);
        s_r8 += __shfl_xor_sync(0xffffffffu, s_r8, 2);
        if (lq == 0) {
            red_s[r0 * 2 + wc]       = s_r;
            red_s[(r0 + 8) * 2 + wc] = s_r8;
        }

        // rescale O accumulators
        const float f0 = row_sc[r0];
        const float f1 = row_sc[r0 + 8];
#pragma unroll
        for (int nt = 0; nt < 8; ++nt) {
            acc_o[nt][0] *= f0; acc_o[nt][1] *= f0;
            acc_o[nt][2] *= f1; acc_o[nt][3] *= f1;
        }
        __syncthreads();

        if (tid < BM)
            row_l[tid] = row_l[tid] * row_sc[tid] + red_s[tid * 2] + red_s[tid * 2 + 1];

        // ---- O += P V : plain fp16, warp m16 x n64 (d-half) ----
#pragma unroll
        for (int ks = 0; ks < BN / 16; ++ks) {
            const int k0 = ks * 16;
            const int kw = ks * 8 + 2 * lq;
            uint2 pa = *reinterpret_cast<const uint2*>(&Ps[r0 * P_ST + kw]);
            uint2 pb = *reinterpret_cast<const uint2*>(&Ps[(r0 + 8) * P_ST + kw]);
#pragma unroll
            for (int nt = 0; nt < 8; ++nt) {
                const int n0 = wc * 64 + nt * 8;
                // banks: (2lq)*132 = 8lq (mod 32), +lr -> disjoint across warp
                float v0 = Vs[(k0 + 2 * lq)     * VS_ST + n0 + lr];
                float v1 = Vs[(k0 + 2 * lq + 1) * VS_ST + n0 + lr];
                float v2 = Vs[(k0 + 2 * lq + 8) * VS_ST + n0 + lr];
                float v3 = Vs[(k0 + 2 * lq + 9) * VS_ST + n0 + lr];
                mma16(acc_o[nt], pa.x, pb.x, pa.y, pb.y,
                      packh2(v0, v1), packh2(v2, v3));
            }
        }
    }

    __syncthreads();

    // ---- normalize + store ----
    const float inv0 = 1.0f / row_l[r0];
    const float inv1 = 1.0f / row_l[r0 + 8];
#pragma unroll
    for (int nt = 0; nt < 8; ++nt) {
        const int d0 = wc * 64 + nt * 8 + 2 * lq;
        float2 oa, ob;
        oa.x = acc_o[nt][0] * inv0; oa.y = acc_o[nt][1] * inv0;
        ob.x = acc_o[nt][2] * inv1; ob.y = acc_o[nt][3] * inv1;
        *reinterpret_cast<float2*>(&gout[(size_t)(qbase + r0) * D_DIM + d0])     = oa;
        *reinterpret_cast<float2*>(&gout[(size_t)(qbase + r0 + 8) * D_DIM + d0]) = ob;
    }
}

extern "C" void kernel_launch(void* const* d_in, const int* in_sizes, int n_in,
                              void* d_out, int out_size) {
    const float* q = (const float*)d_in[0];
    const float* k = (const float*)d_in[1];
    const float* v = (const float*)d_in[2];
    float* out = (float*)d_out;
    (void)in_sizes; (void)n_in; (void)out_size;

    const int smem_bytes = SMEM_WORDS * (int)sizeof(uint32_t);  // ~120 KB
    cudaFuncSetAttribute(fa_f16_kernel,
                         cudaFuncAttributeMaxDynamicSharedMemorySize, smem_bytes);
    fa_f16_kernel<<<S_TOTAL / BM, NTHREADS, smem_bytes>>>(q, k, v, out);
}

// round 8
// speedup vs baseline: 2.9023x; 1.1134x over previous
#include <cuda_runtime.h>
#include <cuda_fp16.h>
#include <math.h>
#include <stdint.h>

// Flash attention, fp16 tensor cores (m16n8k16), fp32 accumulate, FA2-style:
// P stays in registers (QK C-fragment == PV A-fragment layout), softmax fully
// warp-local with per-column-half running (m,l,O) merged once at the end.
// QK^T: 3-term hi/lo fp16 split (~22 mantissa bits) -> score err negligible
// P@V : plain fp16 -> ~2.8e-4 rel err (gate 1e-3)
// S=8192, D=128. CTA: 256 threads (8 warps): 4 row-groups x 2 column-halves.
// Per tile: QK warp m16 x n32 (its half), PV warp m16(k=its 32 cols) x n128.

namespace {
constexpr int S_TOTAL  = 8192;
constexpr int D_DIM    = 128;
constexpr int BM       = 64;
constexpr int BN       = 64;
constexpr int NTHREADS = 256;
constexpr int NTILES   = S_TOTAL / BN;

constexpr int QK_ST = 72;    // Qh/Ql/Kh/Kl row stride in uint32 words (=144 fp16)
constexpr int VS_ST = 132;   // Vs row stride in floats

// smem layout in uint32 words
constexpr int OFF_QH = 0;
constexpr int OFF_QL = OFF_QH + BM * QK_ST;     // 4608
constexpr int OFF_KH = OFF_QL + BM * QK_ST;     // 9216
constexpr int OFF_KL = OFF_KH + BN * QK_ST;     // 13824
constexpr int OFF_V  = OFF_KL + BN * QK_ST;     // 18432 (float region, 64*132)
constexpr int SMEM_WORDS = OFF_V + BN * VS_ST;  // 26880 words = 107520 B
// final-merge scratch (reused over Q tiles after last __syncthreads):
// Obuf = words [0, 8192) (64 rows x 128 d, fp32); Mb/Lb at [8192, 8320)
}  // namespace

__device__ __forceinline__ uint32_t packh2(float a, float b) {
    __half2 h = __floats2half2_rn(a, b);
    return *reinterpret_cast<uint32_t*>(&h);
}

__device__ __forceinline__ void split2_f16(float x, float y, uint32_t& hi, uint32_t& lo) {
    __half hx = __float2half_rn(x);
    __half hy = __float2half_rn(y);
    __half2 hh = __halves2half2(hx, hy);
    hi = *reinterpret_cast<uint32_t*>(&hh);
    lo = packh2(x - __half2float(hx), y - __half2float(hy));
}

__device__ __forceinline__ void mma16(float* c,
                                      uint32_t a0, uint32_t a1, uint32_t a2, uint32_t a3,
                                      uint32_t b0, uint32_t b1) {
    asm volatile(
        "mma.sync.aligned.m16n8k16.row.col.f32.f16.f16.f32 "
        "{%0,%1,%2,%3}, {%4,%5,%6,%7}, {%8,%9}, {%0,%1,%2,%3};\n"
        : "+f"(c[0]), "+f"(c[1]), "+f"(c[2]), "+f"(c[3])
        : "r"(a0), "r"(a1), "r"(a2), "r"(a3), "r"(b0), "r"(b1));
}

// store 4 consecutive k-cols (base 4*c4) of one row, split hi/lo, perm16 layout.
__device__ __forceinline__ void store4_split(uint32_t* rowh, uint32_t* rowl, int c4, float4 v) {
    int blk = c4 >> 2, b = c4 & 3;
    int w0 = blk * 8 + (b & 1) * 4 + (b >> 1);
    uint32_t h01, l01, h23, l23;
    split2_f16(v.x, v.y, h01, l01);
    split2_f16(v.z, v.w, h23, l23);
    rowh[w0]     = h01;
    rowl[w0]     = l01;
    rowh[w0 + 2] = h23;
    rowl[w0 + 2] = l23;
}

__global__ __launch_bounds__(NTHREADS, 1)
void fa_f16_reg_kernel(const float* __restrict__ gq,
                       const float* __restrict__ gk,
                       const float* __restrict__ gv,
                       float* __restrict__ gout) {
    extern __shared__ uint32_t smw[];
    uint32_t* Qh = smw + OFF_QH;
    uint32_t* Ql = smw + OFF_QL;
    uint32_t* Kh = smw + OFF_KH;
    uint32_t* Kl = smw + OFF_KL;
    float* Vs = reinterpret_cast<float*>(smw + OFF_V);

    const int tid  = threadIdx.x;
    const int lane = tid & 31;
    const int warp = tid >> 5;
    const int wr   = warp & 3;       // row group: rows [wr*16, wr*16+16)
    const int wc   = warp >> 2;      // column half (k-half for PV)
    const int lq   = lane & 3;
    const int lr   = lane >> 2;
    const int r0   = wr * 16 + lr;

    const int qbase = blockIdx.x * BM;
    const float4* gq4 = reinterpret_cast<const float4*>(gq);
    const float4* gk4 = reinterpret_cast<const float4*>(gk);
    const float4* gv4 = reinterpret_cast<const float4*>(gv);

    const float sm_scale = 0.08838834764831845f;  // 1/sqrt(128), folded into Q

    // ---- load + scale + split Q tile once ----
#pragma unroll
    for (int it = 0; it < (BM * D_DIM / 4) / NTHREADS; ++it) {
        int idx = it * NTHREADS + tid;
        int row = idx >> 5;
        int c4  = idx & 31;
        float4 v = gq4[(size_t)(qbase + row) * (D_DIM / 4) + c4];
        v.x *= sm_scale; v.y *= sm_scale; v.z *= sm_scale; v.w *= sm_scale;
        store4_split(&Qh[row * QK_ST], &Ql[row * QK_ST], c4, v);
    }

    // per-thread running softmax state for rows r0 and r0+8 (this wc half only)
    float m_run0 = -INFINITY, m_run8 = -INFINITY;
    float l_run0 = 0.0f, l_run8 = 0.0f;   // per-lane partials, reduced over lq at end

    float acc_o[16][4];                    // rows (r0, r0+8) x d = nt*8 + 2lq {+1}
#pragma unroll
    for (int n = 0; n < 16; ++n)
#pragma unroll
        for (int j = 0; j < 4; ++j) acc_o[n][j] = 0.0f;

    for (int t = 0; t < NTILES; ++t) {
        __syncthreads();  // previous tile fully consumed before overwrite
        const int kb = t * BN;

        // ---- fill K (split hi/lo) and V (fp32) ----
#pragma unroll
        for (int it = 0; it < (BN * D_DIM / 4) / NTHREADS; ++it) {
            int idx = it * NTHREADS + tid;
            int row = idx >> 5;
            int c4  = idx & 31;
            float4 v = gk4[(size_t)(kb + row) * (D_DIM / 4) + c4];
            store4_split(&Kh[row * QK_ST], &Kl[row * QK_ST], c4, v);
        }
#pragma unroll
        for (int it = 0; it < (BN * D_DIM / 4) / NTHREADS; ++it) {
            int idx = it * NTHREADS + tid;
            int s   = idx >> 5;
            int c4  = idx & 31;
            float4 v = gv4[(size_t)(kb + s) * (D_DIM / 4) + c4];
            *reinterpret_cast<float4*>(&Vs[s * VS_ST + c4 * 4]) = v;
        }
        __syncthreads();

        // ---- S = (Q*scale) K^T : warp m16 x n32 (its column half), 3-term split ----
        float sc[4][4];
#pragma unroll
        for (int n = 0; n < 4; ++n)
#pragma unroll
            for (int j = 0; j < 4; ++j) sc[n][j] = 0.0f;

#pragma unroll
        for (int ks = 0; ks < D_DIM / 16; ++ks) {
            const int kw = ks * 8 + 2 * lq;
            uint2 a02h = *reinterpret_cast<const uint2*>(&Qh[r0 * QK_ST + kw]);
            uint2 a13h = *reinterpret_cast<const uint2*>(&Qh[(r0 + 8) * QK_ST + kw]);
            uint2 a02l = *reinterpret_cast<const uint2*>(&Ql[r0 * QK_ST + kw]);
            uint2 a13l = *reinterpret_cast<const uint2*>(&Ql[(r0 + 8) * QK_ST + kw]);
#pragma unroll
            for (int nt = 0; nt < 4; ++nt) {
                const int n0 = wc * 32 + nt * 8;
                uint2 bh = *reinterpret_cast<const uint2*>(&Kh[(n0 + lr) * QK_ST + kw]);
                uint2 bl = *reinterpret_cast<const uint2*>(&Kl[(n0 + lr) * QK_ST + kw]);
                mma16(sc[nt], a02h.x, a13h.x, a02h.y, a13h.y, bh.x, bh.y);
                mma16(sc[nt], a02h.x, a13h.x, a02h.y, a13h.y, bl.x, bl.y);
                mma16(sc[nt], a02l.x, a13l.x, a02l.y, a13l.y, bh.x, bh.y);
            }
        }

        // ---- warp-local online softmax over this 32-col half ----
        float mr = -INFINITY, mr8 = -INFINITY;
#pragma unroll
        for (int nt = 0; nt < 4; ++nt) {
            mr  = fmaxf(mr,  fmaxf(sc[nt][0], sc[nt][1]));
            mr8 = fmaxf(mr8, fmaxf(sc[nt][2], sc[nt][3]));
        }
        mr  = fmaxf(mr,  __shfl_xor_sync(0xffffffffu, mr, 1));
        mr  = fmaxf(mr,  __shfl_xor_sync(0xffffffffu, mr, 2));
        mr8 = fmaxf(mr8, __shfl_xor_sync(0xffffffffu, mr8, 1));
        mr8 = fmaxf(mr8, __shfl_xor_sync(0xffffffffu, mr8, 2));

        const float mn0 = fmaxf(m_run0, mr);
        const float mn8 = fmaxf(m_run8, mr8);
        const float f0 = __expf(m_run0 - mn0);   // 0 on first tile
        const float f8 = __expf(m_run8 - mn8);
        m_run0 = mn0; m_run8 = mn8;
        l_run0 *= f0; l_run8 *= f8;

        // exp in place; accumulate per-lane l partials
#pragma unroll
        for (int nt = 0; nt < 4; ++nt) {
            sc[nt][0] = __expf(sc[nt][0] - mn0);
            sc[nt][1] = __expf(sc[nt][1] - mn0);
            sc[nt][2] = __expf(sc[nt][2] - mn8);
            sc[nt][3] = __expf(sc[nt][3] - mn8);
            l_run0 += sc[nt][0] + sc[nt][1];
            l_run8 += sc[nt][2] + sc[nt][3];
        }

        // rescale O accumulators
#pragma unroll
        for (int nt = 0; nt < 16; ++nt) {
            acc_o[nt][0] *= f0; acc_o[nt][1] *= f0;
            acc_o[nt][2] *= f8; acc_o[nt][3] *= f8;
        }

        // ---- O += P V : P from registers, k = this warp's 32 columns, n = full 128 ----
#pragma unroll
        for (int kk = 0; kk < 2; ++kk) {
            const uint32_t a0 = packh2(sc[2 * kk][0],     sc[2 * kk][1]);
            const uint32_t a1 = packh2(sc[2 * kk][2],     sc[2 * kk][3]);
            const uint32_t a2 = packh2(sc[2 * kk + 1][0], sc[2 * kk + 1][1]);
            const uint32_t a3 = packh2(sc[2 * kk + 1][2], sc[2 * kk + 1][3]);
            const int kbase = wc * 32 + kk * 16;
#pragma unroll
            for (int nt = 0; nt < 16; ++nt) {
                const int n0 = nt * 8;
                // banks: 8*lq + lr -> disjoint across warp
                float v0 = Vs[(kbase + 2 * lq)     * VS_ST + n0 + lr];
                float v1 = Vs[(kbase + 2 * lq + 1) * VS_ST + n0 + lr];
                float v2 = Vs[(kbase + 2 * lq + 8) * VS_ST + n0 + lr];
                float v3 = Vs[(kbase + 2 * lq + 9) * VS_ST + n0 + lr];
                mma16(acc_o[nt], a0, a1, a2, a3, packh2(v0, v1), packh2(v2, v3));
            }
        }
    }

    // ---- finalize: reduce l over lq lanes ----
    l_run0 += __shfl_xor_sync(0xffffffffu, l_run0, 1);
    l_run0 += __shfl_xor_sync(0xffffffffu, l_run0, 2);
    l_run8 += __shfl_xor_sync(0xffffffffu, l_run8, 1);
    l_run8 += __shfl_xor_sync(0xffffffffu, l_run8, 2);

    __syncthreads();  // all warps done reading tiles; reuse smem as merge scratch

    float* Ob = reinterpret_cast<float*>(smw);          // [64][128]
    float* Mb = reinterpret_cast<float*>(smw + 8192);   // [64]
    float* Lb = Mb + 64;                                // [64]

    if (wc == 1) {
        if (lq == 0) {
            Mb[r0] = m_run0;     Lb[r0] = l_run0;
            Mb[r0 + 8] = m_run8; Lb[r0 + 8] = l_run8;
        }
#pragma unroll
        for (int nt = 0; nt < 16; ++nt) {
            const int d0 = nt * 8 + 2 * lq;
            Ob[r0 * D_DIM + d0]           = acc_o[nt][0];
            Ob[r0 * D_DIM + d0 + 1]       = acc_o[nt][1];
            Ob[(r0 + 8) * D_DIM + d0]     = acc_o[nt][2];
            Ob[(r0 + 8) * D_DIM + d0 + 1] = acc_o[nt][3];
        }
    }
    __syncthreads();

    if (wc == 0) {
        const float m1_0 = Mb[r0],     l1_0 = Lb[r0];
        const float m1_8 = Mb[r0 + 8], l1_8 = Lb[r0 + 8];
        const float ms0 = fmaxf(m_run0, m1_0);
        const float ms8 = fmaxf(m_run8, m1_8);
        const float e0a = __expf(m_run0 - ms0), e0b = __expf(m1_0 - ms0);
        const float e8a = __expf(m_run8 - ms8), e8b = __expf(m1_8 - ms8);
        const float inv0 = 1.0f / (l_run0 * e0a + l1_0 * e0b);
        const float inv8 = 1.0f / (l_run8 * e8a + l1_8 * e8b);
#pragma unroll
        for (int nt = 0; nt < 16; ++nt) {
            const int d0 = nt * 8 + 2 * lq;
            float2 oa, ob;
            oa.x = (acc_o[nt][0] * e0a + Ob[r0 * D_DIM + d0]           * e0b) * inv0;
            oa.y = (acc_o[nt][1] * e0a + Ob[r0 * D_DIM + d0 + 1]       * e0b) * inv0;
            ob.x = (acc_o[nt][2] * e8a + Ob[(r0 + 8) * D_DIM + d0]     * e8b) * inv8;
            ob.y = (acc_o[nt][3] * e8a + Ob[(r0 + 8) * D_DIM + d0 + 1] * e8b) * inv8;
            *reinterpret_cast<float2*>(&gout[(size_t)(qbase + r0) * D_DIM + d0])     = oa;
            *reinterpret_cast<float2*>(&gout[(size_t)(qbase + r0 + 8) * D_DIM + d0]) = ob;
        }
    }
}

extern "C" void kernel_launch(void* const* d_in, const int* in_sizes, int n_in,
                              void* d_out, int out_size) {
    const float* q = (const float*)d_in[0];
    const float* k = (const float*)d_in[1];
    const float* v = (const float*)d_in[2];
    float* out = (float*)d_out;
    (void)in_sizes; (void)n_in; (void)out_size;

    const int smem_bytes = SMEM_WORDS * (int)sizeof(uint32_t);  // ~105 KB
    cudaFuncSetAttribute(fa_f16_reg_kernel,
                         cudaFuncAttributeMaxDynamicSharedMemorySize, smem_bytes);
    fa_f16_reg_kernel<<<S_TOTAL / BM, NTHREADS, smem_bytes>>>(q, k, v, out);
}